// round 1
// baseline (speedup 1.0000x reference)
#include <cuda_runtime.h>

#define N_NODES 50000
#define DIM     256
#define NEG     0.2f
#define LN_EPS  1e-5f
#define BM      64
#define BK      32

// In-degree masks per relation (scratch; allocation-free per harness rules).
__device__ unsigned char g_mask0[N_NODES];
__device__ unsigned char g_mask1[N_NODES];
__device__ unsigned char g_mask2[N_NODES];

__global__ void zero_mask_kernel(int n) {
    int i = blockIdx.x * blockDim.x + threadIdx.x;
    if (i < n) { g_mask0[i] = 0; g_mask1[i] = 0; g_mask2[i] = 0; }
}

__global__ void scatter_mask_kernel(const int* __restrict__ d0,
                                    const int* __restrict__ d1,
                                    const int* __restrict__ d2, int E) {
    int i = blockIdx.x * blockDim.x + threadIdx.x;
    if (i < E) {
        g_mask0[d0[i]] = 1;
        g_mask1[d1[i]] = 1;
        g_mask2[d2[i]] = 1;
    }
}

__device__ __forceinline__ float head_w(float q, float kv, float n1) {
    // softmax over T=4 slots taking only two distinct values:
    //   n1 slots of z1 = lrelu(q+kv), (4-n1) slots of z0 = lrelu(q)
    // return sum of beta over the m=1 slots.
    float x1 = q + kv;
    float z1 = fmaxf(x1, NEG * x1);
    float z0 = fmaxf(q,  NEG * q);
    float m  = fmaxf(z1, z0);
    float e1 = expf(z1 - m);
    float e0 = expf(z0 - m);
    float f1 = n1 * e1;
    return f1 / (f1 + (4.0f - n1) * e0);
}

// Fused: v = feat @ Wr + br, then per-node metapath-attention weight + ReLU + LayerNorm.
// Block: 256 threads = 8 warps. Tile: BM=64 rows x full 256 cols.
// Thread (ty,tx): ty = warp id (rows ty*8..ty*8+7), tx = lane
//   cols: {tx*4..tx*4+3} and {128+tx*4..128+tx*4+3}  -> acc[8][8]
__global__ __launch_bounds__(256, 2)
void fused_gemm_epilogue(const float* __restrict__ feat,
                         const float* __restrict__ Wr,
                         const float* __restrict__ br,
                         const float* __restrict__ rel_q,
                         const float* __restrict__ rel_k,
                         const float* __restrict__ ln_g,
                         const float* __restrict__ ln_b,
                         float* __restrict__ out, int n)
{
    __shared__ float As[BK][BM + 1];   // transposed A tile, pad->conflict-free scatter
    __shared__ float Bs[BK][DIM];      // B tile (Wr rows)

    const int tid  = threadIdx.x;
    const int tx   = tid & 31;
    const int ty   = tid >> 5;
    const int row0 = blockIdx.x * BM;

    float acc[8][8];
    #pragma unroll
    for (int i = 0; i < 8; i++)
        #pragma unroll
        for (int j = 0; j < 8; j++) acc[i][j] = 0.0f;

    for (int k0 = 0; k0 < DIM; k0 += BK) {
        // --- load A tile: 64 rows x 32 ks, store transposed ---
        #pragma unroll
        for (int p = 0; p < 2; p++) {
            int s   = tid + p * 256;        // 0..511
            int row = s >> 3;               // 0..63
            int kc  = s & 7;                // float4 col 0..7
            int gr  = row0 + row;
            if (gr >= n) gr = n - 1;        // clamp (values unused for OOB rows)
            float4 f = *(const float4*)&feat[(size_t)gr * DIM + k0 + kc * 4];
            As[kc * 4 + 0][row] = f.x;
            As[kc * 4 + 1][row] = f.y;
            As[kc * 4 + 2][row] = f.z;
            As[kc * 4 + 3][row] = f.w;
        }
        // --- load B tile: 32 ks x 256 cols ---
        #pragma unroll
        for (int p = 0; p < 8; p++) {
            int s  = tid + p * 256;         // 0..2047
            int kr = s >> 6;                // 0..31
            int cc = s & 63;                // float4 col 0..63
            *(float4*)&Bs[kr][cc * 4] =
                *(const float4*)&Wr[(size_t)(k0 + kr) * DIM + cc * 4];
        }
        __syncthreads();

        #pragma unroll
        for (int k = 0; k < BK; k++) {
            float a[8];
            #pragma unroll
            for (int i = 0; i < 8; i++) a[i] = As[k][ty * 8 + i];  // broadcast
            float4 b0 = *(const float4*)&Bs[k][tx * 4];
            float4 b1 = *(const float4*)&Bs[k][128 + tx * 4];
            float b[8] = {b0.x, b0.y, b0.z, b0.w, b1.x, b1.y, b1.z, b1.w};
            #pragma unroll
            for (int i = 0; i < 8; i++)
                #pragma unroll
                for (int j = 0; j < 8; j++)
                    acc[i][j] = fmaf(a[i], b[j], acc[i][j]);
        }
        __syncthreads();
    }

    // ---------------- epilogue ----------------
    // Per-lane column constants.
    const int ci = (tx & 15) * 4;        // offset within head
    const int ha = tx >> 4;              // head of cols [0,128)
    const int hb = 2 + (tx >> 4);        // head of cols [128,256)
    float rqa[4], rka[4], rqb[4], rkb[4];
    float bra[4], brb[4], ga[4], gb[4], ba[4], bb[4];
    #pragma unroll
    for (int j = 0; j < 4; j++) {
        rqa[j] = rel_q[ha * 64 + ci + j];
        rka[j] = rel_k[ha * 64 + ci + j];
        rqb[j] = rel_q[hb * 64 + ci + j];
        rkb[j] = rel_k[hb * 64 + ci + j];
        int colA = tx * 4 + j;
        int colB = 128 + tx * 4 + j;
        bra[j] = br[colA];   brb[j] = br[colB];
        ga[j]  = ln_g[colA]; gb[j]  = ln_b ? ln_g[colB] : 0.f; // placeholder fix below
        ba[j]  = ln_b[colA]; bb[j]  = ln_b[colB];
        gb[j]  = ln_g[colB];
    }

    #pragma unroll
    for (int i = 0; i < 8; i++) {
        int row = row0 + ty * 8 + i;     // uniform across warp
        if (row >= n) continue;

        float vv[8];
        #pragma unroll
        for (int j = 0; j < 4; j++) {
            vv[j]     = acc[i][j]     + bra[j];
            vv[4 + j] = acc[i][4 + j] + brb[j];
        }

        // q / kv partials for the lane's two heads
        float pqa = 0.f, pka = 0.f, pqb = 0.f, pkb = 0.f;
        #pragma unroll
        for (int j = 0; j < 4; j++) {
            pqa = fmaf(vv[j],     rqa[j], pqa);
            pka = fmaf(vv[j],     rka[j], pka);
            pqb = fmaf(vv[4 + j], rqb[j], pqb);
            pkb = fmaf(vv[4 + j], rkb[j], pkb);
        }
        // reduce within 16-lane head groups
        #pragma unroll
        for (int o = 8; o; o >>= 1) {
            pqa += __shfl_xor_sync(0xffffffffu, pqa, o);
            pka += __shfl_xor_sync(0xffffffffu, pka, o);
            pqb += __shfl_xor_sync(0xffffffffu, pqb, o);
            pkb += __shfl_xor_sync(0xffffffffu, pkb, o);
        }

        float n1 = 1.0f + (float)g_mask0[row] + (float)g_mask1[row] + (float)g_mask2[row];
        float wa = head_w(pqa, pka, n1);
        float wb = head_w(pqb, pkb, n1);

        float o8[8];
        float s1 = 0.f, s2 = 0.f;
        #pragma unroll
        for (int j = 0; j < 4; j++) {
            o8[j]     = fmaxf(vv[j] * wa, 0.f);
            o8[4 + j] = fmaxf(vv[4 + j] * wb, 0.f);
        }
        #pragma unroll
        for (int j = 0; j < 8; j++) { s1 += o8[j]; s2 = fmaf(o8[j], o8[j], s2); }
        #pragma unroll
        for (int o = 16; o; o >>= 1) {
            s1 += __shfl_xor_sync(0xffffffffu, s1, o);
            s2 += __shfl_xor_sync(0xffffffffu, s2, o);
        }
        float mu  = s1 * (1.0f / 256.0f);
        float var = s2 * (1.0f / 256.0f) - mu * mu;
        float rs  = rsqrtf(var + LN_EPS);

        float4 w0, w1;
        w0.x = (o8[0] - mu) * rs * ga[0] + ba[0];
        w0.y = (o8[1] - mu) * rs * ga[1] + ba[1];
        w0.z = (o8[2] - mu) * rs * ga[2] + ba[2];
        w0.w = (o8[3] - mu) * rs * ga[3] + ba[3];
        w1.x = (o8[4] - mu) * rs * gb[0] + bb[0];
        w1.y = (o8[5] - mu) * rs * gb[1] + bb[1];
        w1.z = (o8[6] - mu) * rs * gb[2] + bb[2];
        w1.w = (o8[7] - mu) * rs * gb[3] + bb[3];
        *(float4*)&out[(size_t)row * DIM + tx * 4]       = w0;
        *(float4*)&out[(size_t)row * DIM + 128 + tx * 4] = w1;
    }
}

extern "C" void kernel_launch(void* const* d_in, const int* in_sizes, int n_in,
                              void* d_out, int out_size)
{
    // Input order per reference setup_inputs():
    // 0 feat, 1 Wl, 2 bl, 3 Wr, 4 br, 5 attn_l, 6 attn_r, 7 rel_q, 8 rel_k,
    // 9 ln_gamma, 10 ln_beta, 11 src0, 12 dst0, 13 src1, 14 dst1, 15 src2, 16 dst2
    const float* feat  = (const float*)d_in[0];
    const float* Wr    = (const float*)d_in[3];
    const float* br    = (const float*)d_in[4];
    const float* rel_q = (const float*)d_in[7];
    const float* rel_k = (const float*)d_in[8];
    const float* ln_g  = (const float*)d_in[9];
    const float* ln_b  = (const float*)d_in[10];
    const int*   dst0  = (const int*)d_in[12];
    const int*   dst1  = (const int*)d_in[14];
    const int*   dst2  = (const int*)d_in[16];

    int n = in_sizes[0] / DIM;   // 50000
    int E = in_sizes[12];        // 400000

    zero_mask_kernel<<<(n + 255) / 256, 256>>>(n);
    scatter_mask_kernel<<<(E + 255) / 256, 256>>>(dst0, dst1, dst2, E);
    fused_gemm_epilogue<<<(n + BM - 1) / BM, 256>>>(
        feat, Wr, br, rel_q, rel_k, ln_g, ln_b, (float*)d_out, n);
}